// round 13
// baseline (speedup 1.0000x reference)
#include <cuda_runtime.h>
#include <cuda_bf16.h>
#include <cstdint>

#define SEQ   4096
#define HID   1024
#define INTER 4096
#define NH    16
#define HD    64

// ---------------- device scratch (no allocations allowed) ----------------
__device__ float          g_xn [SEQ * HID];
__device__ __nv_bfloat16  g_qb [SEQ * HID];
__device__ __nv_bfloat16  g_kb [SEQ * HID];
__device__ __nv_bfloat16  g_vb [SEQ * HID];
__device__ float          g_ctx[SEQ * HID];
__device__ float          g_x1 [SEQ * HID];
__device__ float          g_h  [SEQ * INTER];

// ======================= low-level helpers ================================
__device__ __forceinline__ uint32_t smem_u32(const void* p) {
    uint32_t a;
    asm("{ .reg .u64 t; cvta.to.shared.u64 t, %1; cvt.u32.u64 %0, t; }"
        : "=r"(a) : "l"(p));
    return a;
}
__device__ __forceinline__ float ex2_approx(float x) {
    float r;
    asm("ex2.approx.f32 %0, %1;" : "=f"(r) : "f"(x));
    return r;
}
__device__ __forceinline__ uint32_t pack_bf16(float lo, float hi) {
    uint32_t r;
    asm("cvt.rn.satfinite.bf16x2.f32 %0, %1, %2;" : "=r"(r) : "f"(hi), "f"(lo));
    return r;
}
__device__ __forceinline__ uint32_t f2tf32(float x) {
    uint32_t r;
    asm("cvt.rna.tf32.f32 %0, %1;" : "=r"(r) : "f"(x));
    return r;
}
__device__ __forceinline__ void ldsm4(uint32_t* r, uint32_t addr) {
    asm volatile("ldmatrix.sync.aligned.m8n8.x4.shared.b16 {%0,%1,%2,%3}, [%4];"
        : "=r"(r[0]), "=r"(r[1]), "=r"(r[2]), "=r"(r[3]) : "r"(addr));
}
__device__ __forceinline__ void ldsm4t(uint32_t* r, uint32_t addr) {
    asm volatile("ldmatrix.sync.aligned.m8n8.x4.trans.shared.b16 {%0,%1,%2,%3}, [%4];"
        : "=r"(r[0]), "=r"(r[1]), "=r"(r[2]), "=r"(r[3]) : "r"(addr));
}
// bf16 m16n8k16 (flash)
__device__ __forceinline__ void mma16816(float* d, const uint32_t* a,
                                         const uint32_t* b, const float* c) {
    asm volatile(
        "mma.sync.aligned.m16n8k16.row.col.f32.bf16.bf16.f32 "
        "{%0,%1,%2,%3}, {%4,%5,%6,%7}, {%8,%9}, {%10,%11,%12,%13};"
        : "=f"(d[0]), "=f"(d[1]), "=f"(d[2]), "=f"(d[3])
        : "r"(a[0]), "r"(a[1]), "r"(a[2]), "r"(a[3]),
          "r"(b[0]), "r"(b[1]),
          "f"(c[0]), "f"(c[1]), "f"(c[2]), "f"(c[3]));
}
// tf32 m16n8k8 (gemms)
__device__ __forceinline__ void mma1688(float* d, const uint32_t* a,
                                        const uint32_t* b, const float* c) {
    asm volatile(
        "mma.sync.aligned.m16n8k8.row.col.f32.tf32.tf32.f32 "
        "{%0,%1,%2,%3}, {%4,%5,%6,%7}, {%8,%9}, {%10,%11,%12,%13};"
        : "=f"(d[0]), "=f"(d[1]), "=f"(d[2]), "=f"(d[3])
        : "r"(a[0]), "r"(a[1]), "r"(a[2]), "r"(a[3]),
          "r"(b[0]), "r"(b[1]),
          "f"(c[0]), "f"(c[1]), "f"(c[2]), "f"(c[3]));
}

// ---------------- mean-only layernorm: out = w*(x - mean(x)) + b ----------
__global__ __launch_bounds__(256) void ln_kernel(const float* __restrict__ x,
                                                 const float* __restrict__ w,
                                                 const float* __restrict__ b,
                                                 float* __restrict__ out) {
    int row = blockIdx.x;
    int tid = threadIdx.x;
    const float4* xr = reinterpret_cast<const float4*>(x + (size_t)row * HID);
    float4 xv = xr[tid];
    float s = xv.x + xv.y + xv.z + xv.w;
    #pragma unroll
    for (int o = 16; o; o >>= 1) s += __shfl_xor_sync(0xffffffffu, s, o);
    __shared__ float red[8];
    if ((tid & 31) == 0) red[tid >> 5] = s;
    __syncthreads();
    if (tid < 8) {
        float t = red[tid];
        #pragma unroll
        for (int o = 4; o; o >>= 1) t += __shfl_xor_sync(0xffu, t, o);
        if (tid == 0) red[0] = t;
    }
    __syncthreads();
    float mean = red[0] * (1.0f / HID);
    float4 wv = reinterpret_cast<const float4*>(w)[tid];
    float4 bv = reinterpret_cast<const float4*>(b)[tid];
    float4 ov;
    ov.x = wv.x * (xv.x - mean) + bv.x;
    ov.y = wv.y * (xv.y - mean) + bv.y;
    ov.z = wv.z * (xv.z - mean) + bv.z;
    ov.w = wv.w * (xv.w - mean) + bv.w;
    reinterpret_cast<float4*>(out + (size_t)row * HID)[tid] = ov;
}

// ====================== TF32 single-pass GEMM =============================
// C[M,N] = A[M,K] @ B[N,K]^T + bias (+relu) (+res); optional bf16 output
// (scaled by oscale). CTA tile 128x128, warptile 64x32, k-chunk 16 (2 tf32
// k8 steps), double-buffered smem, LDG->reg prefetch, cvt.rna.tf32 in loader.
// Row stride 80 bytes (64B data + 16B pad): 16B-aligned, ldsm conflict-free.
#define RSTR   80
#define A_T    10240             // 128 rows * 80B
#define STG    20480             // A tile + B tile
#define GSMEM  40960             // 2 stages

template <int RELU, int RES, int OBF16>
__device__ __forceinline__ void hgemm_body(const float* __restrict__ A,
                                           const float* __restrict__ B,
                                           const float* __restrict__ bias,
                                           const float* __restrict__ res,
                                           void* __restrict__ Cout,
                                           int M, int N, int K,
                                           int bx, int by, char* sm,
                                           float oscale) {
    const uint32_t sb = smem_u32(sm);
    const int tid = threadIdx.x, lane = tid & 31, wid = tid >> 5;
    const int wm = (wid >> 2) << 6;       // 0 or 64
    const int wn = (wid & 3) << 5;        // 0,32,64,96
    const int m0 = by << 7, n0 = bx << 7;

    // ldsm lane offsets (byte):
    const int aoff = (lane & 15) * RSTR + ((lane >> 4) << 4);  // 16 rows x 2 col-tiles
    const int boff = (lane & 7) * RSTR + ((lane >> 3) << 4);   // 8 rows x 4 col-tiles

    // loader: thread -> (row tid>>1, 8-float half tid&1) of A and B tiles
    const int lr = tid >> 1, lh = tid & 1;
    const float* Aptr = A + (size_t)(m0 + lr) * K + lh * 8;
    const float* Bptr = B + (size_t)(n0 + lr) * K + lh * 8;
    const uint32_t sdst = lr * RSTR + lh * 32;

    float acc[4][4][4] = {};
    const int NC = K >> 4;

    float4 fa0 = *(const float4*)(Aptr);
    float4 fa1 = *(const float4*)(Aptr + 4);
    float4 fb0 = *(const float4*)(Bptr);
    float4 fb1 = *(const float4*)(Bptr + 4);

    #define CVT_STORE(dst, f0, f1) do {                                       \
        uint4 u0 = make_uint4(f2tf32((f0).x), f2tf32((f0).y),                 \
                              f2tf32((f0).z), f2tf32((f0).w));                \
        uint4 u1 = make_uint4(f2tf32((f1).x), f2tf32((f1).y),                 \
                              f2tf32((f1).z), f2tf32((f1).w));                \
        *(uint4*)(dst)      = u0;                                             \
        *(uint4*)((dst)+16) = u1;                                             \
    } while (0)

    CVT_STORE(sm + sdst, fa0, fa1);
    CVT_STORE(sm + A_T + sdst, fb0, fb1);
    __syncthreads();

    for (int kc = 0; kc < NC; kc++) {
        const uint32_t sta = (kc & 1) * STG;
        if (kc + 1 < NC) {
            const float* Ap = Aptr + (kc + 1) * 16;
            const float* Bp = Bptr + (kc + 1) * 16;
            fa0 = *(const float4*)(Ap);
            fa1 = *(const float4*)(Ap + 4);
            fb0 = *(const float4*)(Bp);
            fb1 = *(const float4*)(Bp + 4);
        }

        // B fragments: 4 n-tiles, each x4 = {k0-3, k4-7, k8-11, k12-15}
        uint32_t bf[4][4];
        #pragma unroll
        for (int j = 0; j < 4; j++)
            ldsm4(bf[j], sb + sta + A_T + (wn + 8 * j) * RSTR + boff);

        #pragma unroll
        for (int i = 0; i < 4; i++) {
            uint32_t a0[4], a1[4];
            const uint32_t ab = sb + sta + (wm + 16 * i) * RSTR + aoff;
            ldsm4(a0, ab);          // kstep 0 (tf32 cols 0-7)
            ldsm4(a1, ab + 32);     // kstep 1 (tf32 cols 8-15)
            #pragma unroll
            for (int j = 0; j < 4; j++) mma1688(acc[i][j], a0, &bf[j][0], acc[i][j]);
            #pragma unroll
            for (int j = 0; j < 4; j++) mma1688(acc[i][j], a1, &bf[j][2], acc[i][j]);
        }

        if (kc + 1 < NC) {
            char* d = sm + ((kc + 1) & 1) * STG + sdst;
            CVT_STORE(d, fa0, fa1);
            CVT_STORE(d + A_T, fb0, fb1);
        }
        __syncthreads();
    }
    #undef CVT_STORE

    // epilogue
    const int g = lane >> 2, t2 = (lane & 3) << 1;
    #pragma unroll
    for (int j = 0; j < 4; j++) {
        const int col = n0 + wn + 8 * j + t2;
        const float bx_ = bias[col], by_ = bias[col + 1];
        #pragma unroll
        for (int i = 0; i < 4; i++) {
            const int row = m0 + wm + 16 * i + g;
            float v0 = acc[i][j][0] + bx_, v1 = acc[i][j][1] + by_;
            float v2 = acc[i][j][2] + bx_, v3 = acc[i][j][3] + by_;
            if (RELU) {
                v0 = fmaxf(v0, 0.f); v1 = fmaxf(v1, 0.f);
                v2 = fmaxf(v2, 0.f); v3 = fmaxf(v3, 0.f);
            }
            if (RES) {
                float2 r0 = *(const float2*)(res + (size_t)row * N + col);
                float2 r1 = *(const float2*)(res + (size_t)(row + 8) * N + col);
                v0 += r0.x; v1 += r0.y; v2 += r1.x; v3 += r1.y;
            }
            if (OBF16) {
                v0 *= oscale; v1 *= oscale; v2 *= oscale; v3 *= oscale;
                __nv_bfloat16* Cb = (__nv_bfloat16*)Cout;
                *(uint32_t*)(Cb + (size_t)row * N + col)       = pack_bf16(v0, v1);
                *(uint32_t*)(Cb + (size_t)(row + 8) * N + col) = pack_bf16(v2, v3);
            } else {
                float* Cf = (float*)Cout;
                *(float2*)(Cf + (size_t)row * N + col)       = make_float2(v0, v1);
                *(float2*)(Cf + (size_t)(row + 8) * N + col) = make_float2(v2, v3);
            }
        }
    }
}

template <int RELU, int RES, int OBF16>
__global__ __launch_bounds__(256, 2) void hgemm(const float* __restrict__ A,
                                                const float* __restrict__ B,
                                                const float* __restrict__ bias,
                                                const float* __restrict__ res,
                                                void* __restrict__ Cout,
                                                int M, int N, int K) {
    extern __shared__ __align__(16) char sm[];
    hgemm_body<RELU, RES, OBF16>(A, B, bias, res, Cout, M, N, K,
                                 blockIdx.x, blockIdx.y, sm, 1.0f);
}

#define CEXP_SCALE 0.18033688f   // 0.125 * log2(e)

// merged q/k/v; Q output pre-scaled into the exp2 domain for flash
__global__ __launch_bounds__(256, 2) void hgemm_qkv(const float* __restrict__ A,
                                                    const float* __restrict__ B0,
                                                    const float* __restrict__ B1,
                                                    const float* __restrict__ B2,
                                                    const float* __restrict__ b0,
                                                    const float* __restrict__ b1,
                                                    const float* __restrict__ b2,
                                                    void* __restrict__ C0,
                                                    void* __restrict__ C1,
                                                    void* __restrict__ C2) {
    extern __shared__ __align__(16) char sm[];
    const int sel = blockIdx.x >> 3;
    const int bx  = blockIdx.x & 7;
    const float* B    = (sel == 0) ? B0 : (sel == 1) ? B1 : B2;
    const float* bias = (sel == 0) ? b0 : (sel == 1) ? b1 : b2;
    void* C           = (sel == 0) ? C0 : (sel == 1) ? C1 : C2;
    const float osc   = (sel == 0) ? CEXP_SCALE : 1.0f;
    hgemm_body<0, 0, 1>(A, B, bias, nullptr, C, SEQ, HID, HID,
                        bx, blockIdx.y, sm, osc);
}

// ====================== HMMA flash attention (pipelined) ===================
#define FL_Q    0
#define FL_K0   18432
#define FL_V0   27648
#define FL_K1   36864
#define FL_V1   46080
#define FL_SMEM 55296

__global__ __launch_bounds__(256, 2) void flash(const __nv_bfloat16* __restrict__ Q,
                                                const __nv_bfloat16* __restrict__ K,
                                                const __nv_bfloat16* __restrict__ V,
                                                float* __restrict__ O) {
    extern __shared__ __align__(16) char fsm[];
    __nv_bfloat16* Qs = (__nv_bfloat16*)(fsm + FL_Q);
    const uint32_t base = smem_u32(fsm);
    const int tid = threadIdx.x, lane = tid & 31, wid = tid >> 5;
    const int q0 = blockIdx.x << 7;
    const int hc = blockIdx.y << 6;

    #pragma unroll
    for (int j = 0; j < 4; j++) {
        int idx = tid + 256 * j;
        int r = idx >> 3, c8 = (idx & 7) << 3;
        *(uint4*)(Qs + r * 72 + c8) =
            *(const uint4*)(Q + (size_t)(q0 + r) * HID + hc + c8);
    }
    __syncthreads();

    uint32_t qf[4][4];
    {
        uint32_t ab = base + FL_Q + (wid * 16 + (lane & 15)) * 144 + (lane >> 4) * 16;
        #pragma unroll
        for (int c = 0; c < 4; c++) ldsm4(qf[c], ab + c * 32);
    }

    const uint32_t kboff = ((lane & 7) + ((lane >> 4) << 3)) * 144 + ((lane & 8) << 1);
    const uint32_t vboff = ((lane & 7) + (lane & 8)) * 144 + (lane >> 4) * 16;

    const int lr = tid >> 3, lc8 = (tid & 7) << 3;
    const __nv_bfloat16* gK = K + (size_t)lr * HID + hc + lc8;
    const __nv_bfloat16* gV = V + (size_t)lr * HID + hc + lc8;
    const uint32_t soff = lr * 144 + lc8 * 2;

    {
        uint4 k0 = *(const uint4*)(gK);
        uint4 k1 = *(const uint4*)(gK + (size_t)32 * HID);
        uint4 v0 = *(const uint4*)(gV);
        uint4 v1 = *(const uint4*)(gV + (size_t)32 * HID);
        *(uint4*)(fsm + FL_K0 + soff)            = k0;
        *(uint4*)(fsm + FL_K0 + soff + 32 * 144) = k1;
        *(uint4*)(fsm + FL_V0 + soff)            = v0;
        *(uint4*)(fsm + FL_V0 + soff + 32 * 144) = v1;
    }
    __syncthreads();

    float o[8][4] = {};
    float m0r = -1e30f, m1r = -1e30f, l0 = 0.f, l1 = 0.f;

    for (int it = 0; it < SEQ / 64; it++) {
        const int st = it & 1;
        const uint32_t kb_base = base + (st ? FL_K1 : FL_K0);
        const uint32_t vb_base = base + (st ? FL_V1 : FL_V0);

        uint4 k0, k1, v0, v1;
        if (it + 1 < SEQ / 64) {
            const size_t go = (size_t)(it + 1) * 64 * HID;
            k0 = *(const uint4*)(gK + go);
            k1 = *(const uint4*)(gK + go + (size_t)32 * HID);
            v0 = *(const uint4*)(gV + go);
            v1 = *(const uint4*)(gV + go + (size_t)32 * HID);
        }

        float s[8][4];
        #pragma unroll
        for (int j = 0; j < 8; j++)
            #pragma unroll
            for (int e = 0; e < 4; e++) s[j][e] = 0.f;
        #pragma unroll
        for (int c = 0; c < 4; c++) {
            uint32_t kb[16];
            #pragma unroll
            for (int h = 0; h < 4; h++)
                ldsm4(kb + 4 * h, kb_base + h * 2304 + kboff + 32 * c);
            #pragma unroll
            for (int j = 0; j < 8; j++) mma16816(s[j], qf[c], kb + 2 * j, s[j]);
        }

        float rm0 = -1e30f, rm1 = -1e30f;
        #pragma unroll
        for (int j = 0; j < 8; j++) {
            rm0 = fmaxf(rm0, fmaxf(s[j][0], s[j][1]));
            rm1 = fmaxf(rm1, fmaxf(s[j][2], s[j][3]));
        }
        rm0 = fmaxf(rm0, __shfl_xor_sync(0xffffffffu, rm0, 1));
        rm0 = fmaxf(rm0, __shfl_xor_sync(0xffffffffu, rm0, 2));
        rm1 = fmaxf(rm1, __shfl_xor_sync(0xffffffffu, rm1, 1));
        rm1 = fmaxf(rm1, __shfl_xor_sync(0xffffffffu, rm1, 2));
        float mn0 = fmaxf(m0r, rm0), mn1 = fmaxf(m1r, rm1);
        float al0 = ex2_approx(m0r - mn0), al1 = ex2_approx(m1r - mn1);
        m0r = mn0; m1r = mn1;
        float rs0 = 0.f, rs1 = 0.f;
        #pragma unroll
        for (int j = 0; j < 8; j++) {
            s[j][0] = ex2_approx(s[j][0] - mn0); rs0 += s[j][0];
            s[j][1] = ex2_approx(s[j][1] - mn0); rs0 += s[j][1];
            s[j][2] = ex2_approx(s[j][2] - mn1); rs1 += s[j][2];
            s[j][3] = ex2_approx(s[j][3] - mn1); rs1 += s[j][3];
        }
        rs0 += __shfl_xor_sync(0xffffffffu, rs0, 1);
        rs0 += __shfl_xor_sync(0xffffffffu, rs0, 2);
        rs1 += __shfl_xor_sync(0xffffffffu, rs1, 1);
        rs1 += __shfl_xor_sync(0xffffffffu, rs1, 2);

        bool noresc = __all_sync(0xffffffffu, (al0 == 1.0f) && (al1 == 1.0f));
        if (noresc) {
            l0 += rs0;
            l1 += rs1;
        } else {
            l0 = l0 * al0 + rs0;
            l1 = l1 * al1 + rs1;
            #pragma unroll
            for (int j = 0; j < 8; j++) {
                o[j][0] *= al0; o[j][1] *= al0;
                o[j][2] *= al1; o[j][3] *= al1;
            }
        }

        uint32_t pa[4][4];
        #pragma unroll
        for (int c = 0; c < 4; c++) {
            pa[c][0] = pack_bf16(s[2 * c][0],     s[2 * c][1]);
            pa[c][1] = pack_bf16(s[2 * c][2],     s[2 * c][3]);
            pa[c][2] = pack_bf16(s[2 * c + 1][0], s[2 * c + 1][1]);
            pa[c][3] = pack_bf16(s[2 * c + 1][2], s[2 * c + 1][3]);
        }
        #pragma unroll
        for (int c = 0; c < 4; c++) {
            uint32_t vb[16];
            #pragma unroll
            for (int h = 0; h < 4; h++)
                ldsm4t(vb + 4 * h, vb_base + c * 2304 + vboff + 32 * h);
            #pragma unroll
            for (int j = 0; j < 8; j++) mma16816(o[j], pa[c], vb + 2 * j, o[j]);
        }

        if (it + 1 < SEQ / 64) {
            char* dk = fsm + (st ? FL_K0 : FL_K1) + soff;
            char* dv = fsm + (st ? FL_V0 : FL_V1) + soff;
            *(uint4*)(dk)            = k0;
            *(uint4*)(dk + 32 * 144) = k1;
            *(uint4*)(dv)            = v0;
            *(uint4*)(dv + 32 * 144) = v1;
        }
        __syncthreads();
    }

    const float inv0 = 1.0f / l0, inv1 = 1.0f / l1;
    #pragma unroll
    for (int j = 0; j < 8; j++) {
        int row = q0 + wid * 16 + (lane >> 2);
        int col = hc + 8 * j + ((lane & 3) << 1);
        *(float2*)(O + (size_t)row * HID + col) =
            make_float2(o[j][0] * inv0, o[j][1] * inv0);
        *(float2*)(O + (size_t)(row + 8) * HID + col) =
            make_float2(o[j][2] * inv1, o[j][3] * inv1);
    }
}

// ---------------- launch --------------------------------------------------
extern "C" void kernel_launch(void* const* d_in, const int* in_sizes, int n_in,
                              void* d_out, int out_size) {
    const float* x     = (const float*)d_in[0];
    const float* an_w  = (const float*)d_in[1];
    const float* an_b  = (const float*)d_in[2];
    const float* q_w   = (const float*)d_in[3];
    const float* q_b   = (const float*)d_in[4];
    const float* k_w   = (const float*)d_in[5];
    const float* k_b   = (const float*)d_in[6];
    const float* v_w   = (const float*)d_in[7];
    const float* v_b   = (const float*)d_in[8];
    const float* o_w   = (const float*)d_in[9];
    const float* o_b   = (const float*)d_in[10];
    const float* fn_w  = (const float*)d_in[11];
    const float* fn_b  = (const float*)d_in[12];
    const float* ff1_w = (const float*)d_in[13];
    const float* ff1_b = (const float*)d_in[14];
    const float* ff2_w = (const float*)d_in[15];
    const float* ff2_b = (const float*)d_in[16];
    float* out = (float*)d_out;

    float *xn, *ctx, *x1, *hbuf;
    __nv_bfloat16 *qb, *kb, *vb;
    cudaGetSymbolAddress((void**)&xn,   g_xn);
    cudaGetSymbolAddress((void**)&qb,   g_qb);
    cudaGetSymbolAddress((void**)&kb,   g_kb);
    cudaGetSymbolAddress((void**)&vb,   g_vb);
    cudaGetSymbolAddress((void**)&ctx,  g_ctx);
    cudaGetSymbolAddress((void**)&x1,   g_x1);
    cudaGetSymbolAddress((void**)&hbuf, g_h);

    cudaFuncSetAttribute(hgemm_qkv, cudaFuncAttributeMaxDynamicSharedMemorySize, GSMEM);
    cudaFuncSetAttribute(hgemm<0, 1, 0>, cudaFuncAttributeMaxDynamicSharedMemorySize, GSMEM);
    cudaFuncSetAttribute(hgemm<1, 0, 0>, cudaFuncAttributeMaxDynamicSharedMemorySize, GSMEM);
    cudaFuncSetAttribute(flash, cudaFuncAttributeMaxDynamicSharedMemorySize, FL_SMEM);

    dim3 g_qkv (3 * HID / 128, SEQ / 128);   // (24, 32) = 768 CTAs
    dim3 g_proj(HID / 128, SEQ / 128);       // (8, 32)
    dim3 g_ff1 (INTER / 128, SEQ / 128);     // (32, 32)

    ln_kernel<<<SEQ, 256>>>(x, an_w, an_b, xn);
    hgemm_qkv<<<g_qkv, 256, GSMEM>>>(xn, q_w, k_w, v_w, q_b, k_b, v_b,
                                     qb, kb, vb);
    flash<<<dim3(SEQ / 128, NH), 256, FL_SMEM>>>(qb, kb, vb, ctx);
    hgemm<0, 1, 0><<<g_proj, 256, GSMEM>>>(ctx, o_w, o_b, x, x1,
                                           SEQ, HID, HID);
    ln_kernel<<<SEQ, 256>>>(x1, fn_w, fn_b, xn);
    hgemm<1, 0, 0><<<g_ff1, 256, GSMEM>>>(xn, ff1_w, ff1_b, nullptr, hbuf,
                                          SEQ, INTER, HID);
    hgemm<0, 1, 0><<<g_proj, 256, GSMEM>>>(hbuf, ff2_w, ff2_b, x1, out,
                                           SEQ, HID, INTER);
}

// round 14
// speedup vs baseline: 1.0314x; 1.0314x over previous
#include <cuda_runtime.h>
#include <cuda_bf16.h>
#include <cstdint>

#define SEQ   4096
#define HID   1024
#define INTER 4096
#define NH    16
#define HD    64

// ---------------- device scratch (no allocations allowed) ----------------
__device__ float          g_xn [SEQ * HID];
__device__ __nv_bfloat16  g_qb [SEQ * HID];
__device__ __nv_bfloat16  g_kb [SEQ * HID];
__device__ __nv_bfloat16  g_vb [SEQ * HID];
__device__ float          g_ctx[SEQ * HID];
__device__ float          g_x1 [SEQ * HID];
__device__ float          g_h  [SEQ * INTER];

// ======================= low-level helpers ================================
__device__ __forceinline__ uint32_t smem_u32(const void* p) {
    uint32_t a;
    asm("{ .reg .u64 t; cvta.to.shared.u64 t, %1; cvt.u32.u64 %0, t; }"
        : "=r"(a) : "l"(p));
    return a;
}
__device__ __forceinline__ float ex2_approx(float x) {
    float r;
    asm("ex2.approx.f32 %0, %1;" : "=f"(r) : "f"(x));
    return r;
}
__device__ __forceinline__ uint32_t pack_bf16(float lo, float hi) {
    uint32_t r;
    asm("cvt.rn.satfinite.bf16x2.f32 %0, %1, %2;" : "=r"(r) : "f"(hi), "f"(lo));
    return r;
}
__device__ __forceinline__ void ldsm4(uint32_t* r, uint32_t addr) {
    asm volatile("ldmatrix.sync.aligned.m8n8.x4.shared.b16 {%0,%1,%2,%3}, [%4];"
        : "=r"(r[0]), "=r"(r[1]), "=r"(r[2]), "=r"(r[3]) : "r"(addr));
}
__device__ __forceinline__ void ldsm4t(uint32_t* r, uint32_t addr) {
    asm volatile("ldmatrix.sync.aligned.m8n8.x4.trans.shared.b16 {%0,%1,%2,%3}, [%4];"
        : "=r"(r[0]), "=r"(r[1]), "=r"(r[2]), "=r"(r[3]) : "r"(addr));
}
__device__ __forceinline__ void mma16816(float* d, const uint32_t* a,
                                         const uint32_t* b, const float* c) {
    asm volatile(
        "mma.sync.aligned.m16n8k16.row.col.f32.bf16.bf16.f32 "
        "{%0,%1,%2,%3}, {%4,%5,%6,%7}, {%8,%9}, {%10,%11,%12,%13};"
        : "=f"(d[0]), "=f"(d[1]), "=f"(d[2]), "=f"(d[3])
        : "r"(a[0]), "r"(a[1]), "r"(a[2]), "r"(a[3]),
          "r"(b[0]), "r"(b[1]),
          "f"(c[0]), "f"(c[1]), "f"(c[2]), "f"(c[3]));
}
__device__ __forceinline__ void split4(float4 a, uint2& hi, uint2& lo) {
    uint32_t h01 = pack_bf16(a.x, a.y);
    uint32_t h23 = pack_bf16(a.z, a.w);
    float hx = __uint_as_float(h01 << 16);
    float hy = __uint_as_float(h01 & 0xffff0000u);
    float hz = __uint_as_float(h23 << 16);
    float hw = __uint_as_float(h23 & 0xffff0000u);
    uint32_t l01 = pack_bf16(a.x - hx, a.y - hy);
    uint32_t l23 = pack_bf16(a.z - hz, a.w - hw);
    hi = make_uint2(h01, h23);
    lo = make_uint2(l01, l23);
}

// ---------------- mean-only layernorm: out = w*(x - mean(x)) + b ----------
__global__ __launch_bounds__(256) void ln_kernel(const float* __restrict__ x,
                                                 const float* __restrict__ w,
                                                 const float* __restrict__ b,
                                                 float* __restrict__ out) {
    int row = blockIdx.x;
    int tid = threadIdx.x;
    const float4* xr = reinterpret_cast<const float4*>(x + (size_t)row * HID);
    float4 xv = xr[tid];
    float s = xv.x + xv.y + xv.z + xv.w;
    #pragma unroll
    for (int o = 16; o; o >>= 1) s += __shfl_xor_sync(0xffffffffu, s, o);
    __shared__ float red[8];
    if ((tid & 31) == 0) red[tid >> 5] = s;
    __syncthreads();
    if (tid < 8) {
        float t = red[tid];
        #pragma unroll
        for (int o = 4; o; o >>= 1) t += __shfl_xor_sync(0xffu, t, o);
        if (tid == 0) red[0] = t;
    }
    __syncthreads();
    float mean = red[0] * (1.0f / HID);
    float4 wv = reinterpret_cast<const float4*>(w)[tid];
    float4 bv = reinterpret_cast<const float4*>(b)[tid];
    float4 ov;
    ov.x = wv.x * (xv.x - mean) + bv.x;
    ov.y = wv.y * (xv.y - mean) + bv.y;
    ov.z = wv.z * (xv.z - mean) + bv.z;
    ov.w = wv.w * (xv.w - mean) + bv.w;
    reinterpret_cast<float4*>(out + (size_t)row * HID)[tid] = ov;
}

// ====================== HMMA split-bf16 GEMM ==============================
// C[M,N] = A[M,K] @ B[N,K]^T + bias (+relu) (+res); optional bf16 output
// (scaled by oscale). CTA tile 128x128, k-chunk 16 fp32.
// 4-stage smem ring, ONE barrier per 2 chunks, write distance +2.
// fp32 emulation: D = Ah*Bh + Ah*Bl + Al*Bh (fp32 accumulators).
#define TILE_B 6144              // one tile: 128 rows * 48B (24 bf16 incl pad)
#define ASTG   12288             // per-stage A block (Ah + Al)
#define BREG   49152             // B region base (after 4 A stages)
#define GSMEM  98304             // 4 stages * (A 12288 + B 12288)

template <int RELU, int RES, int OBF16>
__device__ __forceinline__ void hgemm_body(const float* __restrict__ A,
                                           const float* __restrict__ B,
                                           const float* __restrict__ bias,
                                           const float* __restrict__ res,
                                           void* __restrict__ Cout,
                                           int M, int N, int K,
                                           int bx, int by, char* sm,
                                           float oscale) {
    const uint32_t sb = smem_u32(sm);
    const int tid = threadIdx.x, lane = tid & 31, wid = tid >> 5;
    const int wm = (wid >> 2) << 6;       // 0 or 64
    const int wn = (wid & 3) << 5;        // 0,32,64,96
    const int m0 = by << 7, n0 = bx << 7;
    const int r_ = tid >> 2, c4 = (tid & 3) << 2;

    const int aoff = (lane & 15) * 48 + (lane >> 4) * 16;
    const int boff = ((lane & 7) + ((lane >> 4) << 3)) * 48 + ((lane & 8) << 1);
    const int soff = r_ * 48 + c4 * 2;

    float acc[4][4][4] = {};

    const float* Aptr = A + (size_t)(m0 + r_) * K + c4;
    const float* Bptr = B + (size_t)(n0 + r_) * K + c4;
    const int NC = K >> 4;                // even for all our K

    float4 a0, a1, b0, b1;

    #define LDG_CHUNK(kc) do {                                   \
        const float* Ap = Aptr + (size_t)(kc) * 16;              \
        const float* Bp = Bptr + (size_t)(kc) * 16;              \
        a0 = *(const float4*)(Ap);                               \
        a1 = *(const float4*)(Ap + (size_t)64 * K);              \
        b0 = *(const float4*)(Bp);                               \
        b1 = *(const float4*)(Bp + (size_t)64 * K);              \
    } while (0)

    #define STS_CHUNK(stg) do {                                  \
        char* dA = sm + (stg) * ASTG + soff;                     \
        char* dB = sm + BREG + (stg) * ASTG + soff;              \
        uint2 h, l;                                              \
        split4(a0, h, l);                                        \
        *(uint2*)(dA)          = h;                              \
        *(uint2*)(dA + TILE_B) = l;                              \
        split4(a1, h, l);                                        \
        *(uint2*)(dA + 64 * 48)          = h;                    \
        *(uint2*)(dA + TILE_B + 64 * 48) = l;                    \
        split4(b0, h, l);                                        \
        *(uint2*)(dB)          = h;                              \
        *(uint2*)(dB + TILE_B) = l;                              \
        split4(b1, h, l);                                        \
        *(uint2*)(dB + 64 * 48)          = h;                    \
        *(uint2*)(dB + TILE_B + 64 * 48) = l;                    \
    } while (0)

    #define MMA_CHUNK(stg) do {                                                   \
        const uint32_t sA = sb + (stg) * ASTG;                                    \
        const uint32_t sB = sb + BREG + (stg) * ASTG;                             \
        uint32_t bh[8], bl[8];                                                    \
        ldsm4(bh + 0, sB + (wn +  0) * 48 + boff);                                \
        ldsm4(bh + 4, sB + (wn + 16) * 48 + boff);                                \
        ldsm4(bl + 0, sB + TILE_B + (wn +  0) * 48 + boff);                       \
        ldsm4(bl + 4, sB + TILE_B + (wn + 16) * 48 + boff);                       \
        _Pragma("unroll")                                                         \
        for (int i = 0; i < 4; i++) {                                             \
            uint32_t ah[4];                                                       \
            ldsm4(ah, sA + (wm + 16 * i) * 48 + aoff);                            \
            _Pragma("unroll")                                                     \
            for (int j = 0; j < 4; j++) mma16816(acc[i][j], ah, bh + 2 * j, acc[i][j]); \
            _Pragma("unroll")                                                     \
            for (int j = 0; j < 4; j++) mma16816(acc[i][j], ah, bl + 2 * j, acc[i][j]); \
        }                                                                         \
        _Pragma("unroll")                                                         \
        for (int i = 0; i < 4; i++) {                                             \
            uint32_t al[4];                                                       \
            ldsm4(al, sA + TILE_B + (wm + 16 * i) * 48 + aoff);                   \
            _Pragma("unroll")                                                     \
            for (int j = 0; j < 4; j++) mma16816(acc[i][j], al, bh + 2 * j, acc[i][j]); \
        }                                                                         \
    } while (0)

    // preload stages 0 and 1
    LDG_CHUNK(0);
    STS_CHUNK(0);
    if (NC > 1) { LDG_CHUNK(1); STS_CHUNK(1); }
    __syncthreads();

    for (int kc = 0; kc < NC; kc += 2) {
        // chunk kc: read stage kc&3, write stage (kc+2)&3
        if (kc + 2 < NC) LDG_CHUNK(kc + 2);
        MMA_CHUNK(kc & 3);
        if (kc + 2 < NC) STS_CHUNK((kc + 2) & 3);
        // chunk kc+1: read stage (kc+1)&3, write stage (kc+3)&3
        if (kc + 3 < NC) LDG_CHUNK(kc + 3);
        MMA_CHUNK((kc + 1) & 3);
        if (kc + 3 < NC) STS_CHUNK((kc + 3) & 3);
        __syncthreads();
    }

    #undef LDG_CHUNK
    #undef STS_CHUNK
    #undef MMA_CHUNK

    // epilogue
    const int g = lane >> 2, t2 = (lane & 3) << 1;
    #pragma unroll
    for (int j = 0; j < 4; j++) {
        const int col = n0 + wn + 8 * j + t2;
        const float bx_ = bias[col], by_ = bias[col + 1];
        #pragma unroll
        for (int i = 0; i < 4; i++) {
            const int row = m0 + wm + 16 * i + g;
            float v0 = acc[i][j][0] + bx_, v1 = acc[i][j][1] + by_;
            float v2 = acc[i][j][2] + bx_, v3 = acc[i][j][3] + by_;
            if (RELU) {
                v0 = fmaxf(v0, 0.f); v1 = fmaxf(v1, 0.f);
                v2 = fmaxf(v2, 0.f); v3 = fmaxf(v3, 0.f);
            }
            if (RES) {
                float2 r0 = *(const float2*)(res + (size_t)row * N + col);
                float2 r1 = *(const float2*)(res + (size_t)(row + 8) * N + col);
                v0 += r0.x; v1 += r0.y; v2 += r1.x; v3 += r1.y;
            }
            if (OBF16) {
                v0 *= oscale; v1 *= oscale; v2 *= oscale; v3 *= oscale;
                __nv_bfloat16* Cb = (__nv_bfloat16*)Cout;
                *(uint32_t*)(Cb + (size_t)row * N + col)       = pack_bf16(v0, v1);
                *(uint32_t*)(Cb + (size_t)(row + 8) * N + col) = pack_bf16(v2, v3);
            } else {
                float* Cf = (float*)Cout;
                *(float2*)(Cf + (size_t)row * N + col)       = make_float2(v0, v1);
                *(float2*)(Cf + (size_t)(row + 8) * N + col) = make_float2(v2, v3);
            }
        }
    }
}

template <int RELU, int RES, int OBF16>
__global__ __launch_bounds__(256, 2) void hgemm(const float* __restrict__ A,
                                                const float* __restrict__ B,
                                                const float* __restrict__ bias,
                                                const float* __restrict__ res,
                                                void* __restrict__ Cout,
                                                int M, int N, int K) {
    extern __shared__ __align__(16) char sm[];
    hgemm_body<RELU, RES, OBF16>(A, B, bias, res, Cout, M, N, K,
                                 blockIdx.x, blockIdx.y, sm, 1.0f);
}

#define CEXP_SCALE 0.18033688f   // 0.125 * log2(e)

// merged q/k/v; Q output pre-scaled into the exp2 domain for flash
__global__ __launch_bounds__(256, 2) void hgemm_qkv(const float* __restrict__ A,
                                                    const float* __restrict__ B0,
                                                    const float* __restrict__ B1,
                                                    const float* __restrict__ B2,
                                                    const float* __restrict__ b0,
                                                    const float* __restrict__ b1,
                                                    const float* __restrict__ b2,
                                                    void* __restrict__ C0,
                                                    void* __restrict__ C1,
                                                    void* __restrict__ C2) {
    extern __shared__ __align__(16) char sm[];
    const int sel = blockIdx.x >> 3;
    const int bx  = blockIdx.x & 7;
    const float* B    = (sel == 0) ? B0 : (sel == 1) ? B1 : B2;
    const float* bias = (sel == 0) ? b0 : (sel == 1) ? b1 : b2;
    void* C           = (sel == 0) ? C0 : (sel == 1) ? C1 : C2;
    const float osc   = (sel == 0) ? CEXP_SCALE : 1.0f;
    hgemm_body<0, 0, 1>(A, B, bias, nullptr, C, SEQ, HID, HID,
                        bx, blockIdx.y, sm, osc);
}

// ====================== HMMA flash attention (pipelined) ===================
#define FL_Q    0
#define FL_K0   18432
#define FL_V0   27648
#define FL_K1   36864
#define FL_V1   46080
#define FL_SMEM 55296

__global__ __launch_bounds__(256, 2) void flash(const __nv_bfloat16* __restrict__ Q,
                                                const __nv_bfloat16* __restrict__ K,
                                                const __nv_bfloat16* __restrict__ V,
                                                float* __restrict__ O) {
    extern __shared__ __align__(16) char fsm[];
    __nv_bfloat16* Qs = (__nv_bfloat16*)(fsm + FL_Q);
    const uint32_t base = smem_u32(fsm);
    const int tid = threadIdx.x, lane = tid & 31, wid = tid >> 5;
    const int q0 = blockIdx.x << 7;
    const int hc = blockIdx.y << 6;

    #pragma unroll
    for (int j = 0; j < 4; j++) {
        int idx = tid + 256 * j;
        int r = idx >> 3, c8 = (idx & 7) << 3;
        *(uint4*)(Qs + r * 72 + c8) =
            *(const uint4*)(Q + (size_t)(q0 + r) * HID + hc + c8);
    }
    __syncthreads();

    uint32_t qf[4][4];
    {
        uint32_t ab = base + FL_Q + (wid * 16 + (lane & 15)) * 144 + (lane >> 4) * 16;
        #pragma unroll
        for (int c = 0; c < 4; c++) ldsm4(qf[c], ab + c * 32);
    }

    const uint32_t kboff = ((lane & 7) + ((lane >> 4) << 3)) * 144 + ((lane & 8) << 1);
    const uint32_t vboff = ((lane & 7) + (lane & 8)) * 144 + (lane >> 4) * 16;

    const int lr = tid >> 3, lc8 = (tid & 7) << 3;
    const __nv_bfloat16* gK = K + (size_t)lr * HID + hc + lc8;
    const __nv_bfloat16* gV = V + (size_t)lr * HID + hc + lc8;
    const uint32_t soff = lr * 144 + lc8 * 2;

    {
        uint4 k0 = *(const uint4*)(gK);
        uint4 k1 = *(const uint4*)(gK + (size_t)32 * HID);
        uint4 v0 = *(const uint4*)(gV);
        uint4 v1 = *(const uint4*)(gV + (size_t)32 * HID);
        *(uint4*)(fsm + FL_K0 + soff)            = k0;
        *(uint4*)(fsm + FL_K0 + soff + 32 * 144) = k1;
        *(uint4*)(fsm + FL_V0 + soff)            = v0;
        *(uint4*)(fsm + FL_V0 + soff + 32 * 144) = v1;
    }
    __syncthreads();

    float o[8][4] = {};
    float m0r = -1e30f, m1r = -1e30f, l0 = 0.f, l1 = 0.f;

    for (int it = 0; it < SEQ / 64; it++) {
        const int st = it & 1;
        const uint32_t kb_base = base + (st ? FL_K1 : FL_K0);
        const uint32_t vb_base = base + (st ? FL_V1 : FL_V0);

        uint4 k0, k1, v0, v1;
        if (it + 1 < SEQ / 64) {
            const size_t go = (size_t)(it + 1) * 64 * HID;
            k0 = *(const uint4*)(gK + go);
            k1 = *(const uint4*)(gK + go + (size_t)32 * HID);
            v0 = *(const uint4*)(gV + go);
            v1 = *(const uint4*)(gV + go + (size_t)32 * HID);
        }

        // S = Q @ K^T (already in exp2 domain; Q pre-scaled)
        float s[8][4];
        #pragma unroll
        for (int j = 0; j < 8; j++)
            #pragma unroll
            for (int e = 0; e < 4; e++) s[j][e] = 0.f;
        #pragma unroll
        for (int c = 0; c < 4; c++) {
            uint32_t kb[16];
            #pragma unroll
            for (int h = 0; h < 4; h++)
                ldsm4(kb + 4 * h, kb_base + h * 2304 + kboff + 32 * c);
            #pragma unroll
            for (int j = 0; j < 8; j++) mma16816(s[j], qf[c], kb + 2 * j, s[j]);
        }

        float rm0 = -1e30f, rm1 = -1e30f;
        #pragma unroll
        for (int j = 0; j < 8; j++) {
            rm0 = fmaxf(rm0, fmaxf(s[j][0], s[j][1]));
            rm1 = fmaxf(rm1, fmaxf(s[j][2], s[j][3]));
        }
        rm0 = fmaxf(rm0, __shfl_xor_sync(0xffffffffu, rm0, 1));
        rm0 = fmaxf(rm0, __shfl_xor_sync(0xffffffffu, rm0, 2));
        rm1 = fmaxf(rm1, __shfl_xor_sync(0xffffffffu, rm1, 1));
        rm1 = fmaxf(rm1, __shfl_xor_sync(0xffffffffu, rm1, 2));
        float mn0 = fmaxf(m0r, rm0), mn1 = fmaxf(m1r, rm1);
        float al0 = ex2_approx(m0r - mn0), al1 = ex2_approx(m1r - mn1);
        m0r = mn0; m1r = mn1;
        float rs0 = 0.f, rs1 = 0.f;
        #pragma unroll
        for (int j = 0; j < 8; j++) {
            s[j][0] = ex2_approx(s[j][0] - mn0); rs0 += s[j][0];
            s[j][1] = ex2_approx(s[j][1] - mn0); rs0 += s[j][1];
            s[j][2] = ex2_approx(s[j][2] - mn1); rs1 += s[j][2];
            s[j][3] = ex2_approx(s[j][3] - mn1); rs1 += s[j][3];
        }
        rs0 += __shfl_xor_sync(0xffffffffu, rs0, 1);
        rs0 += __shfl_xor_sync(0xffffffffu, rs0, 2);
        rs1 += __shfl_xor_sync(0xffffffffu, rs1, 1);
        rs1 += __shfl_xor_sync(0xffffffffu, rs1, 2);

        bool noresc = __all_sync(0xffffffffu, (al0 == 1.0f) && (al1 == 1.0f));
        if (noresc) {
            l0 += rs0;
            l1 += rs1;
        } else {
            l0 = l0 * al0 + rs0;
            l1 = l1 * al1 + rs1;
            #pragma unroll
            for (int j = 0; j < 8; j++) {
                o[j][0] *= al0; o[j][1] *= al0;
                o[j][2] *= al1; o[j][3] *= al1;
            }
        }

        uint32_t pa[4][4];
        #pragma unroll
        for (int c = 0; c < 4; c++) {
            pa[c][0] = pack_bf16(s[2 * c][0],     s[2 * c][1]);
            pa[c][1] = pack_bf16(s[2 * c][2],     s[2 * c][3]);
            pa[c][2] = pack_bf16(s[2 * c + 1][0], s[2 * c + 1][1]);
            pa[c][3] = pack_bf16(s[2 * c + 1][2], s[2 * c + 1][3]);
        }
        #pragma unroll
        for (int c = 0; c < 4; c++) {
            uint32_t vb[16];
            #pragma unroll
            for (int h = 0; h < 4; h++)
                ldsm4t(vb + 4 * h, vb_base + c * 2304 + vboff + 32 * h);
            #pragma unroll
            for (int j = 0; j < 8; j++) mma16816(o[j], pa[c], vb + 2 * j, o[j]);
        }

        if (it + 1 < SEQ / 64) {
            char* dk = fsm + (st ? FL_K0 : FL_K1) + soff;
            char* dv = fsm + (st ? FL_V0 : FL_V1) + soff;
            *(uint4*)(dk)            = k0;
            *(uint4*)(dk + 32 * 144) = k1;
            *(uint4*)(dv)            = v0;
            *(uint4*)(dv + 32 * 144) = v1;
        }
        __syncthreads();
    }

    const float inv0 = 1.0f / l0, inv1 = 1.0f / l1;
    #pragma unroll
    for (int j = 0; j < 8; j++) {
        int row = q0 + wid * 16 + (lane >> 2);
        int col = hc + 8 * j + ((lane & 3) << 1);
        *(float2*)(O + (size_t)row * HID + col) =
            make_float2(o[j][0] * inv0, o[j][1] * inv0);
        *(float2*)(O + (size_t)(row + 8) * HID + col) =
            make_float2(o[j][2] * inv1, o[j][3] * inv1);
    }
}

// ---------------- launch --------------------------------------------------
extern "C" void kernel_launch(void* const* d_in, const int* in_sizes, int n_in,
                              void* d_out, int out_size) {
    const float* x     = (const float*)d_in[0];
    const float* an_w  = (const float*)d_in[1];
    const float* an_b  = (const float*)d_in[2];
    const float* q_w   = (const float*)d_in[3];
    const float* q_b   = (const float*)d_in[4];
    const float* k_w   = (const float*)d_in[5];
    const float* k_b   = (const float*)d_in[6];
    const float* v_w   = (const float*)d_in[7];
    const float* v_b   = (const float*)d_in[8];
    const float* o_w   = (const float*)d_in[9];
    const float* o_b   = (const float*)d_in[10];
    const float* fn_w  = (const float*)d_in[11];
    const float* fn_b  = (const float*)d_in[12];
    const float* ff1_w = (const float*)d_in[13];
    const float* ff1_b = (const float*)d_in[14];
    const float* ff2_w = (const float*)d_in[15];
    const float* ff2_b = (const float*)d_in[16];
    float* out = (float*)d_out;

    float *xn, *ctx, *x1, *hbuf;
    __nv_bfloat16 *qb, *kb, *vb;
    cudaGetSymbolAddress((void**)&xn,   g_xn);
    cudaGetSymbolAddress((void**)&qb,   g_qb);
    cudaGetSymbolAddress((void**)&kb,   g_kb);
    cudaGetSymbolAddress((void**)&vb,   g_vb);
    cudaGetSymbolAddress((void**)&ctx,  g_ctx);
    cudaGetSymbolAddress((void**)&x1,   g_x1);
    cudaGetSymbolAddress((void**)&hbuf, g_h);

    cudaFuncSetAttribute(hgemm_qkv, cudaFuncAttributeMaxDynamicSharedMemorySize, GSMEM);
    cudaFuncSetAttribute(hgemm<0, 1, 0>, cudaFuncAttributeMaxDynamicSharedMemorySize, GSMEM);
    cudaFuncSetAttribute(hgemm<1, 0, 0>, cudaFuncAttributeMaxDynamicSharedMemorySize, GSMEM);
    cudaFuncSetAttribute(flash, cudaFuncAttributeMaxDynamicSharedMemorySize, FL_SMEM);

    dim3 g_qkv (3 * HID / 128, SEQ / 128);   // (24, 32) = 768 CTAs
    dim3 g_proj(HID / 128, SEQ / 128);       // (8, 32)
    dim3 g_ff1 (INTER / 128, SEQ / 128);     // (32, 32)

    ln_kernel<<<SEQ, 256>>>(x, an_w, an_b, xn);
    hgemm_qkv<<<g_qkv, 256, GSMEM>>>(xn, q_w, k_w, v_w, q_b, k_b, v_b,
                                     qb, kb, vb);
    flash<<<dim3(SEQ / 128, NH), 256, FL_SMEM>>>(qb, kb, vb, ctx);
    hgemm<0, 1, 0><<<g_proj, 256, GSMEM>>>(ctx, o_w, o_b, x, x1,
                                           SEQ, HID, HID);
    ln_kernel<<<SEQ, 256>>>(x1, fn_w, fn_b, xn);
    hgemm<1, 0, 0><<<g_ff1, 256, GSMEM>>>(xn, ff1_w, ff1_b, nullptr, hbuf,
                                          SEQ, INTER, HID);
    hgemm<0, 1, 0><<<g_proj, 256, GSMEM>>>(hbuf, ff2_w, ff2_b, x1, out,
                                           SEQ, HID, INTER);
}

// round 16
// speedup vs baseline: 1.2626x; 1.2242x over previous
#include <cuda_runtime.h>
#include <cuda_bf16.h>
#include <cstdint>

#define SEQ   4096
#define HID   1024
#define INTER 4096
#define NH    16
#define HD    64

// ---------------- device scratch (no allocations allowed) ----------------
__device__ float          g_xn [SEQ * HID];
__device__ __nv_bfloat16  g_qb [SEQ * HID];
__device__ __nv_bfloat16  g_kb [SEQ * HID];
__device__ __nv_bfloat16  g_vb [SEQ * HID];
__device__ float          g_ctx[SEQ * HID];
__device__ float          g_x1 [SEQ * HID];
__device__ float          g_h  [SEQ * INTER];

// ======================= low-level helpers ================================
__device__ __forceinline__ uint32_t smem_u32(const void* p) {
    uint32_t a;
    asm("{ .reg .u64 t; cvta.to.shared.u64 t, %1; cvt.u32.u64 %0, t; }"
        : "=r"(a) : "l"(p));
    return a;
}
__device__ __forceinline__ float ex2_approx(float x) {
    float r;
    asm("ex2.approx.f32 %0, %1;" : "=f"(r) : "f"(x));
    return r;
}
__device__ __forceinline__ uint32_t pack_bf16(float lo, float hi) {
    uint32_t r;
    asm("cvt.rn.satfinite.bf16x2.f32 %0, %1, %2;" : "=r"(r) : "f"(hi), "f"(lo));
    return r;
}
// pack two fp32 -> f16x2 (lo in lower half)
__device__ __forceinline__ uint32_t pack_f16(float lo, float hi) {
    uint32_t r;
    asm("cvt.rn.f16x2.f32 %0, %1, %2;" : "=r"(r) : "f"(hi), "f"(lo));
    return r;
}
// unpack f16 halves of a packed word back to fp32
__device__ __forceinline__ void unpack_f16(uint32_t p, float& lo, float& hi) {
    asm("{ .reg .f16 a, b; mov.b32 {a, b}, %2;\n\t"
        "cvt.f32.f16 %0, a; cvt.f32.f16 %1, b; }"
        : "=f"(lo), "=f"(hi) : "r"(p));
}
__device__ __forceinline__ void ldsm4(uint32_t* r, uint32_t addr) {
    asm volatile("ldmatrix.sync.aligned.m8n8.x4.shared.b16 {%0,%1,%2,%3}, [%4];"
        : "=r"(r[0]), "=r"(r[1]), "=r"(r[2]), "=r"(r[3]) : "r"(addr));
}
__device__ __forceinline__ void ldsm4t(uint32_t* r, uint32_t addr) {
    asm volatile("ldmatrix.sync.aligned.m8n8.x4.trans.shared.b16 {%0,%1,%2,%3}, [%4];"
        : "=r"(r[0]), "=r"(r[1]), "=r"(r[2]), "=r"(r[3]) : "r"(addr));
}
// bf16 m16n8k16 (flash)
__device__ __forceinline__ void mma16816(float* d, const uint32_t* a,
                                         const uint32_t* b, const float* c) {
    asm volatile(
        "mma.sync.aligned.m16n8k16.row.col.f32.bf16.bf16.f32 "
        "{%0,%1,%2,%3}, {%4,%5,%6,%7}, {%8,%9}, {%10,%11,%12,%13};"
        : "=f"(d[0]), "=f"(d[1]), "=f"(d[2]), "=f"(d[3])
        : "r"(a[0]), "r"(a[1]), "r"(a[2]), "r"(a[3]),
          "r"(b[0]), "r"(b[1]),
          "f"(c[0]), "f"(c[1]), "f"(c[2]), "f"(c[3]));
}
// fp16 m16n8k16 (gemms; fp32 accumulate)
__device__ __forceinline__ void mma16816h(float* d, const uint32_t* a,
                                          const uint32_t* b, const float* c) {
    asm volatile(
        "mma.sync.aligned.m16n8k16.row.col.f32.f16.f16.f32 "
        "{%0,%1,%2,%3}, {%4,%5,%6,%7}, {%8,%9}, {%10,%11,%12,%13};"
        : "=f"(d[0]), "=f"(d[1]), "=f"(d[2]), "=f"(d[3])
        : "r"(a[0]), "r"(a[1]), "r"(a[2]), "r"(a[3]),
          "r"(b[0]), "r"(b[1]),
          "f"(c[0]), "f"(c[1]), "f"(c[2]), "f"(c[3]));
}
// split fp32x4 -> fp16 hi + fp16 residual lo (A operand; ~22-bit accurate)
__device__ __forceinline__ void split4h(float4 a, uint2& hi, uint2& lo) {
    uint32_t h01 = pack_f16(a.x, a.y);
    uint32_t h23 = pack_f16(a.z, a.w);
    float hx, hy, hz, hw;
    unpack_f16(h01, hx, hy);
    unpack_f16(h23, hz, hw);
    uint32_t l01 = pack_f16(a.x - hx, a.y - hy);
    uint32_t l23 = pack_f16(a.z - hz, a.w - hw);
    hi = make_uint2(h01, h23);
    lo = make_uint2(l01, l23);
}
// round fp32x4 -> fp16 (B operand)
__device__ __forceinline__ uint2 cvt4h(float4 a) {
    return make_uint2(pack_f16(a.x, a.y), pack_f16(a.z, a.w));
}

// ---------------- mean-only layernorm: out = w*(x - mean(x)) + b ----------
__global__ __launch_bounds__(256) void ln_kernel(const float* __restrict__ x,
                                                 const float* __restrict__ w,
                                                 const float* __restrict__ b,
                                                 float* __restrict__ out) {
    int row = blockIdx.x;
    int tid = threadIdx.x;
    const float4* xr = reinterpret_cast<const float4*>(x + (size_t)row * HID);
    float4 xv = xr[tid];
    float s = xv.x + xv.y + xv.z + xv.w;
    #pragma unroll
    for (int o = 16; o; o >>= 1) s += __shfl_xor_sync(0xffffffffu, s, o);
    __shared__ float red[8];
    if ((tid & 31) == 0) red[tid >> 5] = s;
    __syncthreads();
    if (tid < 8) {
        float t = red[tid];
        #pragma unroll
        for (int o = 4; o; o >>= 1) t += __shfl_xor_sync(0xffu, t, o);
        if (tid == 0) red[0] = t;
    }
    __syncthreads();
    float mean = red[0] * (1.0f / HID);
    float4 wv = reinterpret_cast<const float4*>(w)[tid];
    float4 bv = reinterpret_cast<const float4*>(b)[tid];
    float4 ov;
    ov.x = wv.x * (xv.x - mean) + bv.x;
    ov.y = wv.y * (xv.y - mean) + bv.y;
    ov.z = wv.z * (xv.z - mean) + bv.z;
    ov.w = wv.w * (xv.w - mean) + bv.w;
    reinterpret_cast<float4*>(out + (size_t)row * HID)[tid] = ov;
}

// ====================== fp16 2-term split GEMM ============================
// C[M,N] = A[M,K] @ B[N,K]^T + bias (+relu) (+res); optional bf16 output
// (scaled by oscale). CTA tile 128x128, k-chunk 16 fp32, double-buffered.
// fp32 emulation: D = Ah*Bh + Al*Bh (A split fp16 hi/lo; B single fp16).
#define TILE_B   6144            // 128 rows * 48B (16 fp16 data + 16B pad)
#define STAGE_B  18432           // Ah, Al, B
#define GSMEM    36864           // 2 stages

template <int RELU, int RES, int OBF16>
__device__ __forceinline__ void hgemm_body(const float* __restrict__ A,
                                           const float* __restrict__ B,
                                           const float* __restrict__ bias,
                                           const float* __restrict__ res,
                                           void* __restrict__ Cout,
                                           int M, int N, int K,
                                           int bx, int by, char* sm,
                                           float oscale) {
    const uint32_t sb = smem_u32(sm);
    const int tid = threadIdx.x, lane = tid & 31, wid = tid >> 5;
    const int wm = (wid >> 2) << 6;       // 0 or 64
    const int wn = (wid & 3) << 5;        // 0,32,64,96
    const int m0 = by << 7, n0 = bx << 7;
    const int r_ = tid >> 2, c4 = (tid & 3) << 2;

    const int aoff = (lane & 15) * 48 + (lane >> 4) * 16;
    const int boff = ((lane & 7) + ((lane >> 4) << 3)) * 48 + ((lane & 8) << 1);
    const int soff = r_ * 48 + c4 * 2;

    float acc[4][4][4] = {};

    const float* Aptr = A + (size_t)(m0 + r_) * K + c4;
    const float* Bptr = B + (size_t)(n0 + r_) * K + c4;
    const int NC = K >> 4;

    float4 a0 = *(const float4*)(Aptr);
    float4 a1 = *(const float4*)(Aptr + (size_t)64 * K);
    float4 b0 = *(const float4*)(Bptr);
    float4 b1 = *(const float4*)(Bptr + (size_t)64 * K);

    // STS stage 0
    {
        uint2 h, l;
        split4h(a0, h, l);
        *(uint2*)(sm + 0 * TILE_B + soff) = h;
        *(uint2*)(sm + 1 * TILE_B + soff) = l;
        split4h(a1, h, l);
        *(uint2*)(sm + 0 * TILE_B + soff + 64 * 48) = h;
        *(uint2*)(sm + 1 * TILE_B + soff + 64 * 48) = l;
        *(uint2*)(sm + 2 * TILE_B + soff)           = cvt4h(b0);
        *(uint2*)(sm + 2 * TILE_B + soff + 64 * 48) = cvt4h(b1);
    }
    __syncthreads();

    for (int kc = 0; kc < NC; kc++) {
        const uint32_t sta = (kc & 1) * STAGE_B;
        if (kc + 1 < NC) {
            const float* Ap = Aptr + (kc + 1) * 16;
            const float* Bp = Bptr + (kc + 1) * 16;
            a0 = *(const float4*)(Ap);
            a1 = *(const float4*)(Ap + (size_t)64 * K);
            b0 = *(const float4*)(Bp);
            b1 = *(const float4*)(Bp + (size_t)64 * K);
        }

        uint32_t bh[8];
        ldsm4(bh + 0, sb + sta + 2 * TILE_B + (wn +  0) * 48 + boff);
        ldsm4(bh + 4, sb + sta + 2 * TILE_B + (wn + 16) * 48 + boff);

        #pragma unroll
        for (int i = 0; i < 4; i++) {
            uint32_t ah[4], al[4];
            ldsm4(ah, sb + sta + (wm + 16 * i) * 48 + aoff);
            ldsm4(al, sb + sta + TILE_B + (wm + 16 * i) * 48 + aoff);
            #pragma unroll
            for (int j = 0; j < 4; j++) mma16816h(acc[i][j], ah, bh + 2 * j, acc[i][j]);
            #pragma unroll
            for (int j = 0; j < 4; j++) mma16816h(acc[i][j], al, bh + 2 * j, acc[i][j]);
        }

        if (kc + 1 < NC) {
            char* d = sm + ((kc + 1) & 1) * STAGE_B;
            uint2 h, l;
            split4h(a0, h, l);
            *(uint2*)(d + 0 * TILE_B + soff) = h;
            *(uint2*)(d + 1 * TILE_B + soff) = l;
            split4h(a1, h, l);
            *(uint2*)(d + 0 * TILE_B + soff + 64 * 48) = h;
            *(uint2*)(d + 1 * TILE_B + soff + 64 * 48) = l;
            *(uint2*)(d + 2 * TILE_B + soff)           = cvt4h(b0);
            *(uint2*)(d + 2 * TILE_B + soff + 64 * 48) = cvt4h(b1);
        }
        __syncthreads();
    }

    // epilogue
    const int g = lane >> 2, t2 = (lane & 3) << 1;
    #pragma unroll
    for (int j = 0; j < 4; j++) {
        const int col = n0 + wn + 8 * j + t2;
        const float bx_ = bias[col], by_ = bias[col + 1];
        #pragma unroll
        for (int i = 0; i < 4; i++) {
            const int row = m0 + wm + 16 * i + g;
            float v0 = acc[i][j][0] + bx_, v1 = acc[i][j][1] + by_;
            float v2 = acc[i][j][2] + bx_, v3 = acc[i][j][3] + by_;
            if (RELU) {
                v0 = fmaxf(v0, 0.f); v1 = fmaxf(v1, 0.f);
                v2 = fmaxf(v2, 0.f); v3 = fmaxf(v3, 0.f);
            }
            if (RES) {
                float2 r0 = *(const float2*)(res + (size_t)row * N + col);
                float2 r1 = *(const float2*)(res + (size_t)(row + 8) * N + col);
                v0 += r0.x; v1 += r0.y; v2 += r1.x; v3 += r1.y;
            }
            if (OBF16) {
                v0 *= oscale; v1 *= oscale; v2 *= oscale; v3 *= oscale;
                __nv_bfloat16* Cb = (__nv_bfloat16*)Cout;
                *(uint32_t*)(Cb + (size_t)row * N + col)       = pack_bf16(v0, v1);
                *(uint32_t*)(Cb + (size_t)(row + 8) * N + col) = pack_bf16(v2, v3);
            } else {
                float* Cf = (float*)Cout;
                *(float2*)(Cf + (size_t)row * N + col)       = make_float2(v0, v1);
                *(float2*)(Cf + (size_t)(row + 8) * N + col) = make_float2(v2, v3);
            }
        }
    }
}

template <int RELU, int RES, int OBF16>
__global__ __launch_bounds__(256, 2) void hgemm(const float* __restrict__ A,
                                                const float* __restrict__ B,
                                                const float* __restrict__ bias,
                                                const float* __restrict__ res,
                                                void* __restrict__ Cout,
                                                int M, int N, int K) {
    extern __shared__ __align__(16) char sm[];
    hgemm_body<RELU, RES, OBF16>(A, B, bias, res, Cout, M, N, K,
                                 blockIdx.x, blockIdx.y, sm, 1.0f);
}

#define CEXP_SCALE 0.18033688f   // 0.125 * log2(e)

// merged q/k/v; Q output pre-scaled into the exp2 domain for flash
__global__ __launch_bounds__(256, 2) void hgemm_qkv(const float* __restrict__ A,
                                                    const float* __restrict__ B0,
                                                    const float* __restrict__ B1,
                                                    const float* __restrict__ B2,
                                                    const float* __restrict__ b0,
                                                    const float* __restrict__ b1,
                                                    const float* __restrict__ b2,
                                                    void* __restrict__ C0,
                                                    void* __restrict__ C1,
                                                    void* __restrict__ C2) {
    extern __shared__ __align__(16) char sm[];
    const int sel = blockIdx.x >> 3;
    const int bx  = blockIdx.x & 7;
    const float* B    = (sel == 0) ? B0 : (sel == 1) ? B1 : B2;
    const float* bias = (sel == 0) ? b0 : (sel == 1) ? b1 : b2;
    void* C           = (sel == 0) ? C0 : (sel == 1) ? C1 : C2;
    const float osc   = (sel == 0) ? CEXP_SCALE : 1.0f;
    hgemm_body<0, 0, 1>(A, B, bias, nullptr, C, SEQ, HID, HID,
                        bx, blockIdx.y, sm, osc);
}

// ====================== HMMA flash attention (pipelined) ===================
#define FL_Q    0
#define FL_K0   18432
#define FL_V0   27648
#define FL_K1   36864
#define FL_V1   46080
#define FL_SMEM 55296

__global__ __launch_bounds__(256, 2) void flash(const __nv_bfloat16* __restrict__ Q,
                                                const __nv_bfloat16* __restrict__ K,
                                                const __nv_bfloat16* __restrict__ V,
                                                float* __restrict__ O) {
    extern __shared__ __align__(16) char fsm[];
    __nv_bfloat16* Qs = (__nv_bfloat16*)(fsm + FL_Q);
    const uint32_t base = smem_u32(fsm);
    const int tid = threadIdx.x, lane = tid & 31, wid = tid >> 5;
    const int q0 = blockIdx.x << 7;
    const int hc = blockIdx.y << 6;

    #pragma unroll
    for (int j = 0; j < 4; j++) {
        int idx = tid + 256 * j;
        int r = idx >> 3, c8 = (idx & 7) << 3;
        *(uint4*)(Qs + r * 72 + c8) =
            *(const uint4*)(Q + (size_t)(q0 + r) * HID + hc + c8);
    }
    __syncthreads();

    uint32_t qf[4][4];
    {
        uint32_t ab = base + FL_Q + (wid * 16 + (lane & 15)) * 144 + (lane >> 4) * 16;
        #pragma unroll
        for (int c = 0; c < 4; c++) ldsm4(qf[c], ab + c * 32);
    }

    const uint32_t kboff = ((lane & 7) + ((lane >> 4) << 3)) * 144 + ((lane & 8) << 1);
    const uint32_t vboff = ((lane & 7) + (lane & 8)) * 144 + (lane >> 4) * 16;

    const int lr = tid >> 3, lc8 = (tid & 7) << 3;
    const __nv_bfloat16* gK = K + (size_t)lr * HID + hc + lc8;
    const __nv_bfloat16* gV = V + (size_t)lr * HID + hc + lc8;
    const uint32_t soff = lr * 144 + lc8 * 2;

    {
        uint4 k0 = *(const uint4*)(gK);
        uint4 k1 = *(const uint4*)(gK + (size_t)32 * HID);
        uint4 v0 = *(const uint4*)(gV);
        uint4 v1 = *(const uint4*)(gV + (size_t)32 * HID);
        *(uint4*)(fsm + FL_K0 + soff)            = k0;
        *(uint4*)(fsm + FL_K0 + soff + 32 * 144) = k1;
        *(uint4*)(fsm + FL_V0 + soff)            = v0;
        *(uint4*)(fsm + FL_V0 + soff + 32 * 144) = v1;
    }
    __syncthreads();

    float o[8][4] = {};
    float m0r = -1e30f, m1r = -1e30f, l0 = 0.f, l1 = 0.f;

    for (int it = 0; it < SEQ / 64; it++) {
        const int st = it & 1;
        const uint32_t kb_base = base + (st ? FL_K1 : FL_K0);
        const uint32_t vb_base = base + (st ? FL_V1 : FL_V0);

        uint4 k0, k1, v0, v1;
        if (it + 1 < SEQ / 64) {
            const size_t go = (size_t)(it + 1) * 64 * HID;
            k0 = *(const uint4*)(gK + go);
            k1 = *(const uint4*)(gK + go + (size_t)32 * HID);
            v0 = *(const uint4*)(gV + go);
            v1 = *(const uint4*)(gV + go + (size_t)32 * HID);
        }

        // S = Q @ K^T (already in exp2 domain; Q pre-scaled)
        float s[8][4];
        #pragma unroll
        for (int j = 0; j < 8; j++)
            #pragma unroll
            for (int e = 0; e < 4; e++) s[j][e] = 0.f;
        #pragma unroll
        for (int c = 0; c < 4; c++) {
            uint32_t kb[16];
            #pragma unroll
            for (int h = 0; h < 4; h++)
                ldsm4(kb + 4 * h, kb_base + h * 2304 + kboff + 32 * c);
            #pragma unroll
            for (int j = 0; j < 8; j++) mma16816(s[j], qf[c], kb + 2 * j, s[j]);
        }

        float rm0 = -1e30f, rm1 = -1e30f;
        #pragma unroll
        for (int j = 0; j < 8; j++) {
            rm0 = fmaxf(rm0, fmaxf(s[j][0], s[j][1]));
            rm1 = fmaxf(rm1, fmaxf(s[j][2], s[j][3]));
        }
        rm0 = fmaxf(rm0, __shfl_xor_sync(0xffffffffu, rm0, 1));
        rm0 = fmaxf(rm0, __shfl_xor_sync(0xffffffffu, rm0, 2));
        rm1 = fmaxf(rm1, __shfl_xor_sync(0xffffffffu, rm1, 1));
        rm1 = fmaxf(rm1, __shfl_xor_sync(0xffffffffu, rm1, 2));
        float mn0 = fmaxf(m0r, rm0), mn1 = fmaxf(m1r, rm1);
        float al0 = ex2_approx(m0r - mn0), al1 = ex2_approx(m1r - mn1);
        m0r = mn0; m1r = mn1;
        float rs0 = 0.f, rs1 = 0.f;
        #pragma unroll
        for (int j = 0; j < 8; j++) {
            s[j][0] = ex2_approx(s[j][0] - mn0); rs0 += s[j][0];
            s[j][1] = ex2_approx(s[j][1] - mn0); rs0 += s[j][1];
            s[j][2] = ex2_approx(s[j][2] - mn1); rs1 += s[j][2];
            s[j][3] = ex2_approx(s[j][3] - mn1); rs1 += s[j][3];
        }
        rs0 += __shfl_xor_sync(0xffffffffu, rs0, 1);
        rs0 += __shfl_xor_sync(0xffffffffu, rs0, 2);
        rs1 += __shfl_xor_sync(0xffffffffu, rs1, 1);
        rs1 += __shfl_xor_sync(0xffffffffu, rs1, 2);

        bool noresc = __all_sync(0xffffffffu, (al0 == 1.0f) && (al1 == 1.0f));
        if (noresc) {
            l0 += rs0;
            l1 += rs1;
        } else {
            l0 = l0 * al0 + rs0;
            l1 = l1 * al1 + rs1;
            #pragma unroll
            for (int j = 0; j < 8; j++) {
                o[j][0] *= al0; o[j][1] *= al0;
                o[j][2] *= al1; o[j][3] *= al1;
            }
        }

        uint32_t pa[4][4];
        #pragma unroll
        for (int c = 0; c < 4; c++) {
            pa[c][0] = pack_bf16(s[2 * c][0],     s[2 * c][1]);
            pa[c][1] = pack_bf16(s[2 * c][2],     s[2 * c][3]);
            pa[c][2] = pack_bf16(s[2 * c + 1][0], s[2 * c + 1][1]);
            pa[c][3] = pack_bf16(s[2 * c + 1][2], s[2 * c + 1][3]);
        }
        #pragma unroll
        for (int c = 0; c < 4; c++) {
            uint32_t vb[16];
            #pragma unroll
            for (int h = 0; h < 4; h++)
                ldsm4t(vb + 4 * h, vb_base + c * 2304 + vboff + 32 * h);
            #pragma unroll
            for (int j = 0; j < 8; j++) mma16816(o[j], pa[c], vb + 2 * j, o[j]);
        }

        if (it + 1 < SEQ / 64) {
            char* dk = fsm + (st ? FL_K0 : FL_K1) + soff;
            char* dv = fsm + (st ? FL_V0 : FL_V1) + soff;
            *(uint4*)(dk)            = k0;
            *(uint4*)(dk + 32 * 144) = k1;
            *(uint4*)(dv)            = v0;
            *(uint4*)(dv + 32 * 144) = v1;
        }
        __syncthreads();
    }

    const float inv0 = 1.0f / l0, inv1 = 1.0f / l1;
    #pragma unroll
    for (int j = 0; j < 8; j++) {
        int row = q0 + wid * 16 + (lane >> 2);
        int col = hc + 8 * j + ((lane & 3) << 1);
        *(float2*)(O + (size_t)row * HID + col) =
            make_float2(o[j][0] * inv0, o[j][1] * inv0);
        *(float2*)(O + (size_t)(row + 8) * HID + col) =
            make_float2(o[j][2] * inv1, o[j][3] * inv1);
    }
}

// ---------------- launch --------------------------------------------------
extern "C" void kernel_launch(void* const* d_in, const int* in_sizes, int n_in,
                              void* d_out, int out_size) {
    const float* x     = (const float*)d_in[0];
    const float* an_w  = (const float*)d_in[1];
    const float* an_b  = (const float*)d_in[2];
    const float* q_w   = (const float*)d_in[3];
    const float* q_b   = (const float*)d_in[4];
    const float* k_w   = (const float*)d_in[5];
    const float* k_b   = (const float*)d_in[6];
    const float* v_w   = (const float*)d_in[7];
    const float* v_b   = (const float*)d_in[8];
    const float* o_w   = (const float*)d_in[9];
    const float* o_b   = (const float*)d_in[10];
    const float* fn_w  = (const float*)d_in[11];
    const float* fn_b  = (const float*)d_in[12];
    const float* ff1_w = (const float*)d_in[13];
    const float* ff1_b = (const float*)d_in[14];
    const float* ff2_w = (const float*)d_in[15];
    const float* ff2_b = (const float*)d_in[16];
    float* out = (float*)d_out;

    float *xn, *ctx, *x1, *hbuf;
    __nv_bfloat16 *qb, *kb, *vb;
    cudaGetSymbolAddress((void**)&xn,   g_xn);
    cudaGetSymbolAddress((void**)&qb,   g_qb);
    cudaGetSymbolAddress((void**)&kb,   g_kb);
    cudaGetSymbolAddress((void**)&vb,   g_vb);
    cudaGetSymbolAddress((void**)&ctx,  g_ctx);
    cudaGetSymbolAddress((void**)&x1,   g_x1);
    cudaGetSymbolAddress((void**)&hbuf, g_h);

    cudaFuncSetAttribute(hgemm_qkv, cudaFuncAttributeMaxDynamicSharedMemorySize, GSMEM);
    cudaFuncSetAttribute(hgemm<0, 1, 0>, cudaFuncAttributeMaxDynamicSharedMemorySize, GSMEM);
    cudaFuncSetAttribute(hgemm<1, 0, 0>, cudaFuncAttributeMaxDynamicSharedMemorySize, GSMEM);
    cudaFuncSetAttribute(flash, cudaFuncAttributeMaxDynamicSharedMemorySize, FL_SMEM);

    dim3 g_qkv (3 * HID / 128, SEQ / 128);   // (24, 32) = 768 CTAs
    dim3 g_proj(HID / 128, SEQ / 128);       // (8, 32)
    dim3 g_ff1 (INTER / 128, SEQ / 128);     // (32, 32)

    ln_kernel<<<SEQ, 256>>>(x, an_w, an_b, xn);
    hgemm_qkv<<<g_qkv, 256, GSMEM>>>(xn, q_w, k_w, v_w, q_b, k_b, v_b,
                                     qb, kb, vb);
    flash<<<dim3(SEQ / 128, NH), 256, FL_SMEM>>>(qb, kb, vb, ctx);
    hgemm<0, 1, 0><<<g_proj, 256, GSMEM>>>(ctx, o_w, o_b, x, x1,
                                           SEQ, HID, HID);
    ln_kernel<<<SEQ, 256>>>(x1, fn_w, fn_b, xn);
    hgemm<1, 0, 0><<<g_ff1, 256, GSMEM>>>(xn, ff1_w, ff1_b, nullptr, hbuf,
                                          SEQ, INTER, HID);
    hgemm<0, 1, 0><<<g_proj, 256, GSMEM>>>(hbuf, ff2_w, ff2_b, x1, out,
                                           SEQ, HID, INTER);
}